// round 11
// baseline (speedup 1.0000x reference)
#include <cuda_runtime.h>
#include <cstdint>

// ---------------- problem constants ----------------
#define CIN   128
#define COUT  256
#define DTOT  1152
#define RCH   18
#define NTILES 2048          // (16384/32) pixel groups x (256/64) channel groups
#define NCTA  296            // 2 per SM x 148 SMs, single wave

// ---------------- device scratch ----------------
__device__ unsigned g_mm[2];
__device__ __align__(16) signed char g_wq[RCH * 4 * 256 * 16];   // [r][seg][m][16]
__device__ __align__(16) signed char g_xq[(size_t)RCH * 3 * 4 * 16384 * 16]; // [r][pl][seg][pix][16]
__device__ float g_xpad[16 * 128 * 34 * 34];                     // zero-padded input
__device__ int   g_ctab[DTOT];                                   // d -> c*1156+dy*34+dx

// ---------------- helpers ----------------
__device__ __forceinline__ unsigned encf(float f) {
    int b = __float_as_int(f);
    return (b < 0) ? ~(unsigned)b : ((unsigned)b | 0x80000000u);
}
__device__ __forceinline__ float decf(unsigned u) {
    int b = (u & 0x80000000u) ? (int)(u & 0x7fffffffu) : ~(int)u;
    return __int_as_float(b);
}
__device__ __forceinline__ void imma(int* d, const unsigned* a, const unsigned* b) {
    asm volatile(
        "mma.sync.aligned.m16n8k32.row.col.s32.s8.s8.s32 "
        "{%0,%1,%2,%3}, {%4,%5,%6,%7}, {%8,%9}, {%0,%1,%2,%3};"
        : "+r"(d[0]), "+r"(d[1]), "+r"(d[2]), "+r"(d[3])
        : "r"(a[0]), "r"(a[1]), "r"(a[2]), "r"(a[3]),
          "r"(b[0]), "r"(b[1]));
}
__device__ __forceinline__ unsigned prmt(unsigned a, unsigned b, unsigned c) {
    unsigned r;
    asm("prmt.b32 %0, %1, %2, %3;" : "=r"(r) : "r"(a), "r"(b), "r"(c));
    return r;
}
__device__ __forceinline__ unsigned pack_b0(int v0, int v1, int v2, int v3) {
    return prmt(prmt((unsigned)v0, (unsigned)v1, 0x0040),
                prmt((unsigned)v2, (unsigned)v3, 0x0040), 0x5410);
}

// ---------------- pre-kernels ----------------
__global__ void k_init_mm() { if (threadIdx.x < 2) g_mm[threadIdx.x] = 0u; }

__global__ void k_minmax(const float* __restrict__ w, int n) {
    unsigned mx = 0u, mn = 0u;
    for (int i = blockIdx.x * blockDim.x + threadIdx.x; i < n;
         i += gridDim.x * blockDim.x) {
        float f = w[i];
        unsigned e0 = encf(f), e1 = encf(-f);
        mx = mx > e0 ? mx : e0;
        mn = mn > e1 ? mn : e1;
    }
    #pragma unroll
    for (int o = 16; o; o >>= 1) {
        unsigned a = __shfl_xor_sync(0xffffffffu, mx, o);
        unsigned b = __shfl_xor_sync(0xffffffffu, mn, o);
        mx = mx > a ? mx : a;
        mn = mn > b ? mn : b;
    }
    if ((threadIdx.x & 31) == 0) {
        atomicMax(&g_mm[0], mx);
        atomicMax(&g_mm[1], mn);
    }
}

// quantize to s8, layout [r][seg][m][16]
__global__ void k_quant(const float* __restrict__ w) {
    int idx = blockIdx.x * blockDim.x + threadIdx.x;
    if (idx >= COUT * DTOT) return;
    float mx = decf(g_mm[0]);
    float mn = -decf(g_mm[1]);
    float scale = 15.0f / (mx - mn + 1e-9f);
    int m = idx / DTOT;
    int d = idx - m * DTOT;
    float q = fminf(fmaxf(rintf(w[idx] * scale), -7.0f), 7.0f);
    int r = d >> 6, kk = d & 63;
    g_wq[((r * 4 + (kk >> 4)) << 12) + m * 16 + (kk & 15)] = (signed char)(int)q;
}

// zero-padded input copy + offset table
__global__ void k_pad(const float* __restrict__ inp) {
    int idx = blockIdx.x * blockDim.x + threadIdx.x;
    if (idx < DTOT) {
        int c = idx / 9, e = idx - 9 * c;
        int dy = e / 3, dx = e - 3 * dy;
        g_ctab[idx] = c * 1156 + dy * 34 + dx;
    }
    const int N = 16 * 128 * 1156;
    if (idx >= N) return;
    int bc = idx / 1156;
    int o  = idx - bc * 1156;
    int yy = o / 34;
    int xx = o - yy * 34;
    float v = 0.0f;
    if ((unsigned)(yy - 1) < 32u && (unsigned)(xx - 1) < 32u)
        v = inp[bc * 1024 + (yy - 1) * 32 + (xx - 1)];
    g_xpad[idx] = v;
}

// im2col + exact 3-plane fixed-point split (scale 2^19)
__global__ __launch_bounds__(256)
void k_im2col() {
    __shared__ int s_ct[64];
    const int bid = blockIdx.x;                 // 0..1151
    const int r   = bid >> 6;
    const int pix = ((bid & 63) << 8) + threadIdx.x;
    const int b   = pix >> 10;
    const int p10 = pix & 1023;
    const int py  = p10 >> 5;
    const int px  = p10 & 31;
    const float* __restrict__ xb = g_xpad + (size_t)b * (128 * 1156) + py * 34 + px;

    if (threadIdx.x < 64) s_ct[threadIdx.x] = g_ctab[r * 64 + threadIdx.x];
    __syncthreads();

    #pragma unroll
    for (int seg = 0; seg < 4; seg++) {
        unsigned lo4[4], md4[4], hi4[4];
        #pragma unroll
        for (int w = 0; w < 4; w++) {
            int vi[4];
            #pragma unroll
            for (int e = 0; e < 4; e++) {
                float v = xb[s_ct[seg * 16 + w * 4 + e]];
                vi[e] = __float2int_rn(v * 524288.0f);
            }
            int t0 = (vi[0] + 128) >> 8, t1 = (vi[1] + 128) >> 8;
            int t2 = (vi[2] + 128) >> 8, t3 = (vi[3] + 128) >> 8;
            int u0 = (t0 + 128) >> 8, u1 = (t1 + 128) >> 8;
            int u2 = (t2 + 128) >> 8, u3 = (t3 + 128) >> 8;
            lo4[w] = pack_b0(vi[0], vi[1], vi[2], vi[3]);
            md4[w] = pack_b0(t0, t1, t2, t3);
            hi4[w] = pack_b0(u0, u1, u2, u3);
        }
        size_t base = ((((size_t)r * 3 + 0) * 4 + seg) * 16384 + pix) * 16;
        *(uint4*)&g_xq[base] = make_uint4(hi4[0], hi4[1], hi4[2], hi4[3]);
        base = ((((size_t)r * 3 + 1) * 4 + seg) * 16384 + pix) * 16;
        *(uint4*)&g_xq[base] = make_uint4(md4[0], md4[1], md4[2], md4[3]);
        base = ((((size_t)r * 3 + 2) * 4 + seg) * 16384 + pix) * 16;
        *(uint4*)&g_xq[base] = make_uint4(lo4[0], lo4[1], lo4[2], lo4[3]);
    }
}

// ---------------- main kernel: barrier-free, L2-direct, af double-buffered ----------------
__device__ __forceinline__ void load_af(unsigned af[2][2][2][4],
                                        const signed char* __restrict__ xq,
                                        int r, const unsigned pixoff[2][2]) {
    #pragma unroll
    for (int pl = 0; pl < 2; pl++) {
        const unsigned pbase = (unsigned)(r * 3 + pl) << 20;
        #pragma unroll
        for (int mt = 0; mt < 2; mt++)
            #pragma unroll
            for (int ks = 0; ks < 2; ks++)
                #pragma unroll
                for (int q = 0; q < 4; q++) {
                    const unsigned seg = (unsigned)(ks * 2 + (q >> 1));
                    af[pl][mt][ks][q] = *(const unsigned*)
                        (xq + pbase + (seg << 18) + pixoff[mt][q & 1]);
                }
    }
}

__device__ __forceinline__ void compute_chunk(
    const unsigned af[2][2][2][4],
    const signed char* __restrict__ xq, const signed char* __restrict__ wq,
    int r, int gp0, int ch0, int lane, unsigned* cnt) {

    #pragma unroll
    for (int ng = 0; ng < 4; ng++) {
        unsigned bf[2][2][2];   // [ntl][ks][q]
        #pragma unroll
        for (int ntl = 0; ntl < 2; ntl++) {
            const unsigned n = (unsigned)(ch0 + ng * 16 + ntl * 8 + (lane >> 2));
            #pragma unroll
            for (int ks = 0; ks < 2; ks++)
                #pragma unroll
                for (int q = 0; q < 2; q++)
                    bf[ntl][ks][q] = *(const unsigned*)
                        (wq + ((unsigned)(r * 4 + ks * 2 + q) << 12)
                            + n * 16u + (unsigned)(lane & 3) * 4u);
        }

        int acc[4][4];          // [mt*2+ntl][q]
        #pragma unroll
        for (int t = 0; t < 4; t++)
            #pragma unroll
            for (int q = 0; q < 4; q++) acc[t][q] = 0;

        #pragma unroll
        for (int pl = 0; pl < 2; pl++) {
            if (pl) {
                #pragma unroll
                for (int t = 0; t < 4; t++)
                    #pragma unroll
                    for (int q = 0; q < 4; q++) acc[t][q] <<= 8;
            }
            #pragma unroll
            for (int mt = 0; mt < 2; mt++)
                #pragma unroll
                for (int ntl = 0; ntl < 2; ntl++) {
                    imma(acc[mt * 2 + ntl], af[pl][mt][0], bf[ntl][0]);
                    imma(acc[mt * 2 + ntl], af[pl][mt][1], bf[ntl][1]);
                }
        }

        const int gg = ng >> 1, ngl = ng & 1;

        unsigned cm = 0u;
        #pragma unroll
        for (int t = 0; t < 4; t++) {
            const int mt = t >> 1, ntl = t & 1;
            unsigned inc = 0;
            #pragma unroll
            for (int q = 0; q < 4; q++) {
                int v = acc[t][q];
                inc |= ((unsigned)(~v) >> 31) << (8 * q);
                if ((unsigned)(v + 224) <= 448u) cm |= 1u << (t * 4 + q);
            }
            cnt[gg * 8 + mt * 4 + ngl * 2 + ntl] += inc;
        }

        // exact lo-plane fixup (rare), straight from L2
        while (cm) {
            const int i = __ffs(cm) - 1;
            cm &= cm - 1;
            const int t = i >> 2, q = i & 3;
            const int mt = t >> 1, ntl = t & 1;
            const int row = gp0 + mt * 16 + (lane >> 2) + ((q & 2) ? 8 : 0);
            const int col = ch0 + ng * 16 + ntl * 8 + 2 * (lane & 3) + (q & 1);
            int slo = 0;
            #pragma unroll
            for (int kk = 0; kk < 16; kk++) {
                const int xl = *(const int*)
                    (xq + ((unsigned)(r * 3 + 2) << 20)
                        + ((unsigned)(kk >> 2) << 18)
                        + (unsigned)row * 16u + (unsigned)(kk & 3) * 4u);
                const int wc = *(const int*)
                    (wq + ((unsigned)(r * 4 + (kk >> 2)) << 12)
                        + (unsigned)col * 16u + (unsigned)(kk & 3) * 4u);
                slo = __dp4a(xl, wc, slo);
            }
            const int S = (acc[t][q] << 8) + slo;
            const unsigned ob = (unsigned)(~acc[t][q]) >> 31;
            const unsigned nb = (unsigned)(~S) >> 31;
            cnt[gg * 8 + mt * 4 + ngl * 2 + ntl] += (nb - ob) << (8 * q);
        }
    }
}

__global__ __launch_bounds__(256, 2)
void k_onn_main(float* __restrict__ out) {
    const int tid  = threadIdx.x;
    const int lane = tid & 31;
    const int wid  = tid >> 5;
    const int bid  = blockIdx.x;

    // per-CTA tile strip [s0, s1); warp picks one tile (rotated by bid)
    const int s0 = (bid * NTILES) / NCTA;
    const int s1 = ((bid + 1) * NTILES) / NCTA;
    const int widx = (wid + bid) & 7;
    if (widx >= s1 - s0) return;
    const int tile = s0 + widx;

    const int pg  = tile >> 2;          // pixel group (32 pixels)
    const int cg  = tile & 3;           // channel group (64 channels)
    const int gp0 = pg * 32;
    const int ch0 = cg * 64;

    const signed char* __restrict__ xq = g_xq;
    const signed char* __restrict__ wq = g_wq;

    unsigned pixoff[2][2];
    #pragma unroll
    for (int mt = 0; mt < 2; mt++)
        #pragma unroll
        for (int qh = 0; qh < 2; qh++)
            pixoff[mt][qh] = (unsigned)(gp0 + mt * 16 + (lane >> 2) + qh * 8) * 16u
                           + (unsigned)(lane & 3) * 4u;

    unsigned cnt[16];
    #pragma unroll
    for (int i = 0; i < 16; i++) cnt[i] = 0u;

    // ---- software-pipelined chunk loop (double-buffered A fragments) ----
    unsigned af0[2][2][2][4], af1[2][2][2][4];
    load_af(af0, xq, 0, pixoff);

    #pragma unroll 1
    for (int r = 0; r < RCH; r += 2) {
        load_af(af1, xq, r + 1, pixoff);                 // r+1 <= 17 always
        compute_chunk(af0, xq, wq, r, gp0, ch0, lane, cnt);
        if (r + 2 < RCH) load_af(af0, xq, r + 2, pixoff);
        compute_chunk(af1, xq, wq, r + 1, gp0, ch0, lane, cnt);
    }

    // ---- coalesced store via warp shuffle transpose, two 32-ch groups ----
    const int b   = gp0 >> 10;
    const int p10 = gp0 & 1023;
    #pragma unroll
    for (int gg = 0; gg < 2; gg++) {
        float* __restrict__ ob = out + (size_t)b * (COUT * 1024)
                               + (size_t)(ch0 + gg * 32) * 1024 + p10;
        #pragma unroll
        for (int nt = 0; nt < 4; nt++) {
            const unsigned va = cnt[gg * 8 + nt];
            const unsigned vb = cnt[gg * 8 + 4 + nt];
            #pragma unroll
            for (int c8 = 0; c8 < 8; c8++) {
                const int src = ((lane & 7) << 2) + (c8 >> 1);
                unsigned sa = __shfl_sync(0xffffffffu, va, src);
                unsigned sx = __shfl_sync(0xffffffffu, vb, src);
                unsigned v  = (lane & 16) ? sx : sa;
                const int byte = ((lane >> 3) & 1) * 2 + (c8 & 1);
                const float fv = (float)((v >> (byte * 8)) & 255u);
                ob[(size_t)(nt * 8 + c8) * 1024 + lane] = fv;
            }
        }
    }
}

// ---------------- launcher ----------------
extern "C" void kernel_launch(void* const* d_in, const int* in_sizes, int n_in,
                              void* d_out, int out_size) {
    const float* inp    = (const float*)d_in[0];  // [16,128,32,32]
    const float* weight = (const float*)d_in[1];  // [256,128,3,3]
    float* out          = (float*)d_out;          // [16,256,32,32]

    const int nw   = COUT * DTOT;
    const int npad = 16 * 128 * 34 * 34;

    k_init_mm<<<1, 32>>>();
    k_minmax<<<256, 256>>>(weight, nw);
    k_quant<<<(nw + 255) / 256, 256>>>(weight);
    k_pad<<<(npad + 255) / 256, 256>>>(inp);
    k_im2col<<<RCH * 64, 256>>>();
    k_onn_main<<<NCTA, 256>>>(out);
}

// round 12
// speedup vs baseline: 1.0335x; 1.0335x over previous
#include <cuda_runtime.h>
#include <cstdint>

// ---------------- problem constants ----------------
#define CIN   128
#define COUT  256
#define DTOT  1152
#define RCH   18
#define NTILES 2048          // (16384/32) pixel groups x (256/64) channel groups
#define NCTA  296            // 2 per SM x 148 SMs, single wave

#define PADROW 36            // padded row stride (34 used + 2), float4-aligned
#define PADIMG (34 * PADROW) // 1224 floats per (b,c) image

// ---------------- device scratch ----------------
__device__ unsigned g_mm[2] = {0u, 0u};
__device__ __align__(16) signed char g_wq[RCH * 4 * 256 * 16];   // [r][seg][m][16]
__device__ __align__(16) signed char g_xq[(size_t)RCH * 3 * 4 * 16384 * 16]; // [r][pl][seg][pix][16]
__device__ __align__(16) float g_xpad[16 * 128 * PADIMG];        // zero-padded input
__device__ int   g_ctab[DTOT];                                   // d -> c*PADIMG+dy*PADROW+dx

// ---------------- helpers ----------------
__device__ __forceinline__ unsigned encf(float f) {
    int b = __float_as_int(f);
    return (b < 0) ? ~(unsigned)b : ((unsigned)b | 0x80000000u);
}
__device__ __forceinline__ float decf(unsigned u) {
    int b = (u & 0x80000000u) ? (int)(u & 0x7fffffffu) : ~(int)u;
    return __int_as_float(b);
}
__device__ __forceinline__ void imma(int* d, const unsigned* a, const unsigned* b) {
    asm volatile(
        "mma.sync.aligned.m16n8k32.row.col.s32.s8.s8.s32 "
        "{%0,%1,%2,%3}, {%4,%5,%6,%7}, {%8,%9}, {%0,%1,%2,%3};"
        : "+r"(d[0]), "+r"(d[1]), "+r"(d[2]), "+r"(d[3])
        : "r"(a[0]), "r"(a[1]), "r"(a[2]), "r"(a[3]),
          "r"(b[0]), "r"(b[1]));
}
__device__ __forceinline__ unsigned prmt(unsigned a, unsigned b, unsigned c) {
    unsigned r;
    asm("prmt.b32 %0, %1, %2, %3;" : "=r"(r) : "r"(a), "r"(b), "r"(c));
    return r;
}
__device__ __forceinline__ unsigned pack_b0(int v0, int v1, int v2, int v3) {
    return prmt(prmt((unsigned)v0, (unsigned)v1, 0x0040),
                prmt((unsigned)v2, (unsigned)v3, 0x0040), 0x5410);
}

// ---------------- pre-kernels ----------------
__global__ void k_minmax(const float* __restrict__ w, int n) {
    unsigned mx = 0u, mn = 0u;
    for (int i = blockIdx.x * blockDim.x + threadIdx.x; i < n;
         i += gridDim.x * blockDim.x) {
        float f = w[i];
        unsigned e0 = encf(f), e1 = encf(-f);
        mx = mx > e0 ? mx : e0;
        mn = mn > e1 ? mn : e1;
    }
    #pragma unroll
    for (int o = 16; o; o >>= 1) {
        unsigned a = __shfl_xor_sync(0xffffffffu, mx, o);
        unsigned b = __shfl_xor_sync(0xffffffffu, mn, o);
        mx = mx > a ? mx : a;
        mn = mn > b ? mn : b;
    }
    if ((threadIdx.x & 31) == 0) {
        atomicMax(&g_mm[0], mx);
        atomicMax(&g_mm[1], mn);
    }
}

// quantize to s8, layout [r][seg][m][16]
__global__ void k_quant(const float* __restrict__ w) {
    int idx = blockIdx.x * blockDim.x + threadIdx.x;
    if (idx >= COUT * DTOT) return;
    float mx = decf(g_mm[0]);
    float mn = -decf(g_mm[1]);
    float scale = 15.0f / (mx - mn + 1e-9f);
    int m = idx / DTOT;
    int d = idx - m * DTOT;
    float q = fminf(fmaxf(rintf(w[idx] * scale), -7.0f), 7.0f);
    int r = d >> 6, kk = d & 63;
    g_wq[((r * 4 + (kk >> 4)) << 12) + m * 16 + (kk & 15)] = (signed char)(int)q;
}

// zero-padded input copy (float4 stores) + offset table
__global__ void k_pad(const float* __restrict__ inp) {
    int idx = blockIdx.x * blockDim.x + threadIdx.x;
    if (idx < DTOT) {
        int c = idx / 9, e = idx - 9 * c;
        int dy = e / 3, dx = e - 3 * dy;
        g_ctab[idx] = c * PADIMG + dy * PADROW + dx;
    }
    const int N4 = 16 * 128 * (PADIMG / 4);     // 626688 float4s
    if (idx >= N4) return;
    int bc  = idx / (PADIMG / 4);
    int rem = idx - bc * (PADIMG / 4);
    int yy  = rem / (PADROW / 4);
    int c4  = rem - yy * (PADROW / 4);
    const float* src = inp + bc * 1024 + (yy - 1) * 32;
    float4 v;
    #pragma unroll
    for (int j = 0; j < 4; j++) {
        int x = c4 * 4 + j;
        float f = 0.0f;
        if ((unsigned)(yy - 1) < 32u && (unsigned)(x - 1) < 32u)
            f = src[x - 1];
        ((float*)&v)[j] = f;
    }
    *(float4*)&g_xpad[(size_t)bc * PADIMG + yy * PADROW + c4 * 4] = v;
}

// im2col + exact 3-plane fixed-point split (scale 2^19)
__global__ __launch_bounds__(256)
void k_im2col() {
    __shared__ int s_ct[64];
    const int bid = blockIdx.x;                 // 0..1151
    const int r   = bid >> 6;
    const int pix = ((bid & 63) << 8) + threadIdx.x;
    const int b   = pix >> 10;
    const int p10 = pix & 1023;
    const int py  = p10 >> 5;
    const int px  = p10 & 31;
    const float* __restrict__ xb =
        g_xpad + (size_t)b * (128 * PADIMG) + py * PADROW + px;

    if (threadIdx.x < 64) s_ct[threadIdx.x] = g_ctab[r * 64 + threadIdx.x];
    __syncthreads();

    #pragma unroll
    for (int seg = 0; seg < 4; seg++) {
        unsigned lo4[4], md4[4], hi4[4];
        #pragma unroll
        for (int w = 0; w < 4; w++) {
            int vi[4];
            #pragma unroll
            for (int e = 0; e < 4; e++) {
                float v = xb[s_ct[seg * 16 + w * 4 + e]];
                vi[e] = __float2int_rn(v * 524288.0f);
            }
            int t0 = (vi[0] + 128) >> 8, t1 = (vi[1] + 128) >> 8;
            int t2 = (vi[2] + 128) >> 8, t3 = (vi[3] + 128) >> 8;
            int u0 = (t0 + 128) >> 8, u1 = (t1 + 128) >> 8;
            int u2 = (t2 + 128) >> 8, u3 = (t3 + 128) >> 8;
            lo4[w] = pack_b0(vi[0], vi[1], vi[2], vi[3]);
            md4[w] = pack_b0(t0, t1, t2, t3);
            hi4[w] = pack_b0(u0, u1, u2, u3);
        }
        size_t base = ((((size_t)r * 3 + 0) * 4 + seg) * 16384 + pix) * 16;
        *(uint4*)&g_xq[base] = make_uint4(hi4[0], hi4[1], hi4[2], hi4[3]);
        base = ((((size_t)r * 3 + 1) * 4 + seg) * 16384 + pix) * 16;
        *(uint4*)&g_xq[base] = make_uint4(md4[0], md4[1], md4[2], md4[3]);
        base = ((((size_t)r * 3 + 2) * 4 + seg) * 16384 + pix) * 16;
        *(uint4*)&g_xq[base] = make_uint4(lo4[0], lo4[1], lo4[2], lo4[3]);
    }
}

// ---------------- main kernel: barrier-free, all 64 frag loads hoisted ----------------
__global__ __launch_bounds__(256, 2)
void k_onn_main(float* __restrict__ out) {
    const int tid  = threadIdx.x;
    const int lane = tid & 31;
    const int wid  = tid >> 5;
    const int bid  = blockIdx.x;

    // per-CTA tile strip [s0, s1); warp picks one tile (rotated by bid)
    const int s0 = (bid * NTILES) / NCTA;
    const int s1 = ((bid + 1) * NTILES) / NCTA;
    const int widx = (wid + bid) & 7;
    if (widx >= s1 - s0) return;
    const int tile = s0 + widx;

    const int pg  = tile >> 2;          // pixel group (32 pixels)
    const int cg  = tile & 3;           // channel group (64 channels)
    const int gp0 = pg * 32;
    const int ch0 = cg * 64;

    const signed char* __restrict__ xq = g_xq;
    const signed char* __restrict__ wq = g_wq;

    unsigned pixoff[2][2];
    #pragma unroll
    for (int mt = 0; mt < 2; mt++)
        #pragma unroll
        for (int qh = 0; qh < 2; qh++)
            pixoff[mt][qh] = (unsigned)(gp0 + mt * 16 + (lane >> 2) + qh * 8) * 16u
                           + (unsigned)(lane & 3) * 4u;

    unsigned cnt[16];
    #pragma unroll
    for (int i = 0; i < 16; i++) cnt[i] = 0u;

    #pragma unroll 1
    for (int r = 0; r < RCH; r++) {
        // ---- ALL fragment loads for this chunk, issued back-to-back ----
        unsigned af[2][2][2][4];       // [pl][mt][ks][q]  : 32 LDG
        #pragma unroll
        for (int pl = 0; pl < 2; pl++) {
            const unsigned pbase = (unsigned)(r * 3 + pl) << 20;
            #pragma unroll
            for (int mt = 0; mt < 2; mt++)
                #pragma unroll
                for (int ks = 0; ks < 2; ks++)
                    #pragma unroll
                    for (int q = 0; q < 4; q++) {
                        const unsigned seg = (unsigned)(ks * 2 + (q >> 1));
                        af[pl][mt][ks][q] = *(const unsigned*)
                            (xq + pbase + (seg << 18) + pixoff[mt][q & 1]);
                    }
        }
        unsigned bfa[4][2][2][2];      // [ng][ntl][ks][q] : 32 LDG
        #pragma unroll
        for (int ng = 0; ng < 4; ng++)
            #pragma unroll
            for (int ntl = 0; ntl < 2; ntl++) {
                const unsigned n = (unsigned)(ch0 + ng * 16 + ntl * 8 + (lane >> 2));
                #pragma unroll
                for (int ks = 0; ks < 2; ks++)
                    #pragma unroll
                    for (int q = 0; q < 2; q++)
                        bfa[ng][ntl][ks][q] = *(const unsigned*)
                            (wq + ((unsigned)(r * 4 + ks * 2 + q) << 12)
                                + n * 16u + (unsigned)(lane & 3) * 4u);
            }

        // ---- compute: four 16-channel slices ----
        #pragma unroll
        for (int ng = 0; ng < 4; ng++) {
            int acc[4][4];          // [mt*2+ntl][q]
            #pragma unroll
            for (int t = 0; t < 4; t++)
                #pragma unroll
                for (int q = 0; q < 4; q++) acc[t][q] = 0;

            #pragma unroll
            for (int pl = 0; pl < 2; pl++) {
                if (pl) {
                    #pragma unroll
                    for (int t = 0; t < 4; t++)
                        #pragma unroll
                        for (int q = 0; q < 4; q++) acc[t][q] <<= 8;
                }
                #pragma unroll
                for (int mt = 0; mt < 2; mt++)
                    #pragma unroll
                    for (int ntl = 0; ntl < 2; ntl++) {
                        imma(acc[mt * 2 + ntl], af[pl][mt][0], bfa[ng][ntl][0]);
                        imma(acc[mt * 2 + ntl], af[pl][mt][1], bfa[ng][ntl][1]);
                    }
            }

            const int gg = ng >> 1, ngl = ng & 1;

            unsigned cm = 0u;
            #pragma unroll
            for (int t = 0; t < 4; t++) {
                const int mt = t >> 1, ntl = t & 1;
                unsigned inc = 0;
                #pragma unroll
                for (int q = 0; q < 4; q++) {
                    int v = acc[t][q];
                    inc |= ((unsigned)(~v) >> 31) << (8 * q);
                    if ((unsigned)(v + 224) <= 448u) cm |= 1u << (t * 4 + q);
                }
                cnt[gg * 8 + mt * 4 + ngl * 2 + ntl] += inc;
            }

            // exact lo-plane fixup (rare), straight from L2
            while (cm) {
                const int i = __ffs(cm) - 1;
                cm &= cm - 1;
                const int t = i >> 2, q = i & 3;
                const int mt = t >> 1, ntl = t & 1;
                const int row = gp0 + mt * 16 + (lane >> 2) + ((q & 2) ? 8 : 0);
                const int col = ch0 + ng * 16 + ntl * 8 + 2 * (lane & 3) + (q & 1);
                int slo = 0;
                #pragma unroll
                for (int kk = 0; kk < 16; kk++) {
                    const int xl = *(const int*)
                        (xq + ((unsigned)(r * 3 + 2) << 20)
                            + ((unsigned)(kk >> 2) << 18)
                            + (unsigned)row * 16u + (unsigned)(kk & 3) * 4u);
                    const int wc = *(const int*)
                        (wq + ((unsigned)(r * 4 + (kk >> 2)) << 12)
                            + (unsigned)col * 16u + (unsigned)(kk & 3) * 4u);
                    slo = __dp4a(xl, wc, slo);
                }
                const int S = (acc[t][q] << 8) + slo;
                const unsigned ob = (unsigned)(~acc[t][q]) >> 31;
                const unsigned nb = (unsigned)(~S) >> 31;
                cnt[gg * 8 + mt * 4 + ngl * 2 + ntl] += (nb - ob) << (8 * q);
            }
        }
    }

    // ---- coalesced store via warp shuffle transpose, two 32-ch groups ----
    const int b   = gp0 >> 10;
    const int p10 = gp0 & 1023;
    #pragma unroll
    for (int gg = 0; gg < 2; gg++) {
        float* __restrict__ ob = out + (size_t)b * (COUT * 1024)
                               + (size_t)(ch0 + gg * 32) * 1024 + p10;
        #pragma unroll
        for (int nt = 0; nt < 4; nt++) {
            const unsigned va = cnt[gg * 8 + nt];
            const unsigned vb = cnt[gg * 8 + 4 + nt];
            #pragma unroll
            for (int c8 = 0; c8 < 8; c8++) {
                const int src = ((lane & 7) << 2) + (c8 >> 1);
                unsigned sa = __shfl_sync(0xffffffffu, va, src);
                unsigned sx = __shfl_sync(0xffffffffu, vb, src);
                unsigned v  = (lane & 16) ? sx : sa;
                const int byte = ((lane >> 3) & 1) * 2 + (c8 & 1);
                const float fv = (float)((v >> (byte * 8)) & 255u);
                ob[(size_t)(nt * 8 + c8) * 1024 + lane] = fv;
            }
        }
    }
}

// ---------------- launcher ----------------
extern "C" void kernel_launch(void* const* d_in, const int* in_sizes, int n_in,
                              void* d_out, int out_size) {
    const float* inp    = (const float*)d_in[0];  // [16,128,32,32]
    const float* weight = (const float*)d_in[1];  // [256,128,3,3]
    float* out          = (float*)d_out;          // [16,256,32,32]

    const int nw = COUT * DTOT;
    const int n4 = 16 * 128 * (PADIMG / 4);

    k_minmax<<<256, 256>>>(weight, nw);
    k_quant<<<(nw + 255) / 256, 256>>>(weight);
    k_pad<<<(n4 + 255) / 256, 256>>>(inp);
    k_im2col<<<RCH * 64, 256>>>();
    k_onn_main<<<NCTA, 256>>>(out);
}